// round 4
// baseline (speedup 1.0000x reference)
#include <cuda_runtime.h>

// Hopf oscillator CPG step, reformulated:
//   sin(psi_j - psi_i - phi_ij) = (s_j c_i - c_j s_i)cos(phi) - (c_j c_i + s_j s_i)sin(phi)
// A_ij = w_zd*cos(phi_zd), B_ij = w_zd*sin(phi_zd), x_j = r_j s_j, y_j = r_j c_j:
//   coupling_i = c_i*(A x - B y)_i - s_i*(A y + B x)_i
// R4: ONE fused j-loop over 8 rows/warp (16 f32x2 accumulators) so the smem matrix
// read (LDS.64/j) amortizes over 8 rows; regs ~80 -> 3 CTAs/SM; grid 1024.

#define PI2F 6.28318530717958647692f

typedef unsigned long long u64;

__device__ __forceinline__ u64 pack2(float lo, float hi) {
    u64 r;
    asm("mov.b64 %0, {%1, %2};" : "=l"(r) : "f"(lo), "f"(hi));
    return r;
}
__device__ __forceinline__ void unpack2(u64 v, float& lo, float& hi) {
    asm("mov.b64 {%0, %1}, %2;" : "=f"(lo), "=f"(hi) : "l"(v));
}
#define FMA2(acc, a, b) asm("fma.rn.f32x2 %0, %1, %2, %0;" : "+l"(acc) : "l"(a), "l"(b))

__device__ __forceinline__ float fsigmoid(float x) {
    return 1.0f / (1.0f + __expf(-x));
}

__global__ __launch_bounds__(256, 3)
void hopf_kernel(const float* __restrict__ in, float* __restrict__ out,
                 const float* __restrict__ v, const float* __restrict__ b,
                 const float* __restrict__ c, const float* __restrict__ w,
                 const float* __restrict__ phi, int nrows) {
    const int tid  = threadIdx.x;
    const int lane = tid & 31;          // oscillator index i
    const int wib  = tid >> 5;          // warp in block (0..7)
    const int gw   = blockIdx.x * 8 + wib;

    // sAB[j*32 + i] = {A[i][j], B[i][j]}  -> lane-consecutive LDS.64, conflict-free
    __shared__ float2 sAB[1024];
    __shared__ float4 sXY[8][4][32];    // per-warp, per row-pair {x0,x1,y0,y1}

    // ---- build activation matrix in smem (4 entries per thread) ----
    #pragma unroll
    for (int k = 0; k < 4; k++) {
        int m = tid + k * 256;          // flat index, i = m/32, j = m%32
        float A = 0.0f, Bv = 0.0f;
        if (m % 33 != 0) {              // zero-diag: diagonal iff m % 33 == 0
            int kk = m / 33;            // 0..30
            int jj = m % 33 - 1;        // 0..31
            float wa = fsigmoid(w[kk * 32 + jj]);           // W_MAX = 1
            float pa = PI2F * fsigmoid(phi[kk * 32 + jj]);  // PHI_MAX = 2*pi
            float sp, cp;
            __sincosf(pa, &sp, &cp);
            A  = wa * cp;
            Bv = wa * sp;
        }
        sAB[(m & 31) * 32 + (m >> 5)] = make_float2(A, Bv);  // store [j][i]
    }

    // per-lane activations
    const float tpv = (PI2F * 5.0f) * fsigmoid(v[lane]);
    const float ba  = 2.0f  * fsigmoid(b[lane]);
    const float ca  = 10.0f * fsigmoid(c[lane]);

    __syncthreads();

    const int rowBase = gw * 8;         // 8 rows per warp, single fused j-loop
    float sv[8], cv[8];

    // ---- prologue: load 8 rows, sincos, write r_d / r_d_dot, stage x,y ----
    #pragma unroll
    for (int t = 0; t < 8; t++) {
        const int row = rowBase + t;
        float psi = 0.0f, rr = 0.0f, rd = 0.0f;
        if (row < nrows) {
            const float* rp = in + (size_t)row * 96;
            psi = rp[lane];
            rr  = rp[32 + lane];
            rd  = rp[64 + lane];
        }
        __sincosf(psi, &sv[t], &cv[t]);
        float x = rr * sv[t];
        float y = rr * cv[t];
        // pack into row-pair buffers: [p] = rows (2p, 2p+1)
        if ((t & 1) == 0) {
            sXY[wib][t >> 1][lane].x = x;
            sXY[wib][t >> 1][lane].z = y;
        } else {
            sXY[wib][t >> 1][lane].y = x;
            sXY[wib][t >> 1][lane].w = y;
        }
        if (row < nrows) {
            float rdd = ca * (0.25f * ca * (ba - rr) - rd);
            float* op = out + (size_t)row * 96;
            op[32 + lane] = rd;
            op[64 + lane] = rdd;
        }
    }
    __syncwarp();

    // ---- fused matvec: 16 accumulators, 4 row-pairs ----
    // per pair p: P1=sum(Ax), P2=sum(By), Q1=sum(Ay), Q2=sum(Bx)
    u64 P1[4] = {0,0,0,0}, P2[4] = {0,0,0,0};
    u64 Q1[4] = {0,0,0,0}, Q2[4] = {0,0,0,0};

    #pragma unroll
    for (int j = 0; j < 32; j++) {
        float2 ab = sAB[j * 32 + lane];        // LDS.64, conflict-free
        u64 AA = pack2(ab.x, ab.x);
        u64 BB = pack2(ab.y, ab.y);
        #pragma unroll
        for (int p = 0; p < 4; p++) {
            ulonglong2 pp = *reinterpret_cast<const ulonglong2*>(&sXY[wib][p][j]);
            FMA2(P1[p], AA, pp.x);  FMA2(P2[p], BB, pp.y);
            FMA2(Q1[p], AA, pp.y);  FMA2(Q2[p], BB, pp.x);
        }
    }

    // ---- epilogue: combine + psi_dot store ----
    #pragma unroll
    for (int p = 0; p < 4; p++) {
        float p1l,p1h,p2l,p2h,q1l,q1h,q2l,q2h;
        unpack2(P1[p],p1l,p1h); unpack2(P2[p],p2l,p2h);
        unpack2(Q1[p],q1l,q1h); unpack2(Q2[p],q2l,q2h);
        float Pe = p1l - p2l, Po = p1h - p2h;
        float Qe = q1l + q2l, Qo = q1h + q2h;

        const int re = rowBase + 2 * p;
        if (re < nrows)
            out[(size_t)re * 96 + lane] = tpv + cv[2*p] * Pe - sv[2*p] * Qe;
        const int ro = re + 1;
        if (ro < nrows)
            out[(size_t)ro * 96 + lane] = tpv + cv[2*p+1] * Po - sv[2*p+1] * Qo;
    }
}

extern "C" void kernel_launch(void* const* d_in, const int* in_sizes, int n_in,
                              void* d_out, int out_size) {
    const float* states = (const float*)d_in[0];
    const float* v      = (const float*)d_in[1];
    const float* b      = (const float*)d_in[2];
    const float* c      = (const float*)d_in[3];
    const float* w      = (const float*)d_in[4];
    const float* phi    = (const float*)d_in[5];
    float* out = (float*)d_out;

    const int nrows = in_sizes[0] / 96;     // 65536
    const int rows_per_warp = 8;
    const int warps  = (nrows + rows_per_warp - 1) / rows_per_warp;
    const int blocks = (warps + 7) / 8;     // 8 warps (256 threads) per block

    hopf_kernel<<<blocks, 256>>>(states, out, v, b, c, w, phi, nrows);
}